// round 6
// baseline (speedup 1.0000x reference)
#include <cuda_runtime.h>
#include <cstdint>

// SPP: out = concat(x, pool5(x), pool9(x), pool13(x)) along channels.
// pool9 = pool5(pool5(x)), pool13 = pool5(pool9); separable 1-D passes.
// R6: 2 planes per block, cp.async double-buffered input prefetch (plane1's
//     load overlaps plane0's compute), bulk-group async stores (R5).

#define PLANE_F4    1024    // 64*64 / 4 (64 rows x 16 float4)
#define PLANE_BYTES 16384
#define THREADS     256
#define NBLOCKS     4096    // 8192 planes / 2

__device__ __forceinline__ uint32_t smem_u32(const void* p) {
    return (uint32_t)__cvta_generic_to_shared(p);
}
__device__ __forceinline__ void bulk_store(void* gdst, uint32_t ssrc) {
    asm volatile("cp.async.bulk.global.shared::cta.bulk_group [%0], [%1], %2;"
                 :: "l"(gdst), "r"(ssrc), "n"(PLANE_BYTES) : "memory");
    asm volatile("cp.async.bulk.commit_group;" ::: "memory");
}
template <int N> __device__ __forceinline__ void bulk_wait() {
    asm volatile("cp.async.bulk.wait_group %0;" :: "n"(N) : "memory");
}
__device__ __forceinline__ void fence_async() {
    asm volatile("fence.proxy.async.shared::cta;" ::: "memory");
}
__device__ __forceinline__ void cpa16(uint32_t s, const void* g) {
    asm volatile("cp.async.cg.shared.global [%0], [%1], 16;" :: "r"(s), "l"(g) : "memory");
}
__device__ __forceinline__ void cpa_commit() {
    asm volatile("cp.async.commit_group;" ::: "memory");
}
template <int N> __device__ __forceinline__ void cpa_wait() {
    asm volatile("cp.async.wait_group %0;" :: "n"(N) : "memory");
}

__device__ __forceinline__ float4 v4max(float4 a, float4 b) {
    return make_float4(fmaxf(a.x, b.x), fmaxf(a.y, b.y),
                       fmaxf(a.z, b.z), fmaxf(a.w, b.w));
}

// 5-wide horizontal max over [p.z p.w | c.x c.y c.z c.w | n.x n.y]
__device__ __forceinline__ float4 hmax5(float4 p, float4 c, float4 n) {
    float m01 = fmaxf(c.x, c.y);
    float m23 = fmaxf(c.z, c.w);
    float m0123 = fmaxf(m01, m23);
    float4 o;
    o.x = fmaxf(fmaxf(p.z, p.w), fmaxf(m01, c.z));
    o.y = fmaxf(p.w, m0123);
    o.z = fmaxf(m0123, n.x);
    o.w = fmaxf(fmaxf(c.y, m23), fmaxf(n.x, n.y));
    return o;
}

// Three cascaded pool5 stages; cur holds the current v-plane, nxt is scratch.
// Bulk stores are pipelined: wait<1> before any buffer overwrite guarantees
// every store except the most recent (whose source is never `nxt`) has drained.
__device__ __forceinline__ void run_pools(
    float4 v[4], float4*& cur, float4*& nxt,
    float4* out0, int base, int xg, int yg, int tid)
{
    const float NEG = __int_as_float(0xff800000);
    const float4 NEG4 = make_float4(NEG, NEG, NEG, NEG);

    #pragma unroll
    for (int pool = 0; pool < 3; pool++) {
        // horizontal pass: center from regs, neighbor columns from cur
        float4 h[4];
        #pragma unroll
        for (int r = 0; r < 4; r++) {
            int t = base + (r << 4);
            float4 p  = (xg > 0)  ? cur[t - 1] : NEG4;
            float4 nx = (xg < 15) ? cur[t + 1] : NEG4;
            h[r] = hmax5(p, v[r], nx);
        }
        if (tid == 0) bulk_wait<1>();        // nxt's old store drained
        __syncthreads();
        #pragma unroll
        for (int r = 0; r < 4; r++) nxt[base + (r << 4)] = h[r];
        __syncthreads();

        // vertical pass: my 4 h-rows in regs + 2 above + 2 below from nxt
        float4 u0 = (yg > 0)  ? nxt[base - 32] : NEG4;
        float4 u1 = (yg > 0)  ? nxt[base - 16] : NEG4;
        float4 d0 = (yg < 15) ? nxt[base + 64] : NEG4;
        float4 d1 = (yg < 15) ? nxt[base + 80] : NEG4;

        float4 m12 = v4max(h[1], h[2]);
        v[0] = v4max(v4max(u0, u1), v4max(h[0], m12));
        v[1] = v4max(v4max(u1, h[0]), v4max(m12, h[3]));
        v[2] = v4max(v4max(h[0], m12), v4max(h[3], d0));
        v[3] = v4max(v4max(m12, h[3]), v4max(d0, d1));

        __syncthreads();                     // all v-pass reads of nxt done
        #pragma unroll
        for (int r = 0; r < 4; r++) nxt[base + (r << 4)] = v[r];
        __syncthreads();                     // v-plane complete in nxt
        if (tid == 0) {
            fence_async();
            bulk_store(out0 + (size_t)(pool + 1) * 512 * PLANE_F4, smem_u32(nxt));
        }
        float4* tmp = cur; cur = nxt; nxt = tmp;
    }
}

__global__ __launch_bounds__(THREADS, 4)
void spp_kernel(const float4* __restrict__ in, float4* __restrict__ out) {
    __shared__ float4 W0[PLANE_F4];
    __shared__ float4 W1[PLANE_F4];
    __shared__ float4 IN[PLANE_F4];

    const int p0  = blockIdx.x << 1;        // first plane of the pair
    const int tid = threadIdx.x;
    const int xg = tid & 15;                // float4 column 0..15
    const int yg = tid >> 4;                // row-strip 0..15
    const int base = ((yg << 2) << 4) + xg;

    const float4* src0 = in + (size_t)p0 * PLANE_F4;
    const float4* src1 = src0 + PLANE_F4;

    // async-load both planes: group A -> W0 (plane0), group B -> IN (plane1)
    #pragma unroll
    for (int r = 0; r < 4; r++) {
        int t = base + (r << 4);
        cpa16(smem_u32(&W0[t]), &src0[t]);
    }
    cpa_commit();
    #pragma unroll
    for (int r = 0; r < 4; r++) {
        int t = base + (r << 4);
        cpa16(smem_u32(&IN[t]), &src1[t]);
    }
    cpa_commit();

    // ---- plane 0 ----
    int n = p0 >> 9, c = p0 & 511;
    float4* out0 = out + ((size_t)n * 2048 + c) * PLANE_F4;

    cpa_wait<1>();                          // plane0 landed in W0
    __syncthreads();
    float4 v[4];
    #pragma unroll
    for (int r = 0; r < 4; r++) v[r] = W0[base + (r << 4)];
    if (tid == 0) { fence_async(); bulk_store(out0, smem_u32(W0)); }

    float4* cur = W0;
    float4* nxt = W1;
    run_pools(v, cur, nxt, out0, base, xg, yg, tid);
    // post: cur == W1 (source of latest store), nxt == W0

    // ---- plane 1 ----
    const int p1 = p0 + 1;
    n = p1 >> 9; c = p1 & 511;
    float4* out1 = out + ((size_t)n * 2048 + c) * PLANE_F4;

    cpa_wait<0>();                          // plane1 landed in IN
    __syncthreads();
    #pragma unroll
    for (int r = 0; r < 4; r++) v[r] = IN[base + (r << 4)];
    if (tid == 0) { fence_async(); bulk_store(out1, smem_u32(IN)); }

    cur = IN;
    nxt = W0;
    run_pools(v, cur, nxt, out1, base, xg, yg, tid);

    if (tid == 0) bulk_wait<0>();           // drain before CTA exit
}

extern "C" void kernel_launch(void* const* d_in, const int* in_sizes, int n_in,
                              void* d_out, int out_size) {
    const float4* x = (const float4*)d_in[0];
    float4* out = (float4*)d_out;
    spp_kernel<<<NBLOCKS, THREADS>>>(x, out);
}

// round 8
// speedup vs baseline: 1.0303x; 1.0303x over previous
#include <cuda_runtime.h>
#include <cstdint>

// SPP: out = concat(x, pool5(x), pool9(x), pool13(x)) along channels.
// pool9 = pool5(pool5(x)), pool13 = pool5(pool9); separable 1-D passes.
// R8 = R5 + L2 policy split (fixed PTX syntax):
//     input loads  : ld.global.L2::cache_hint + evict_last policy
//     output stores: cp.async.bulk ... .L2::cache_hint + evict_first policy

#define NPLANES   8192      // 16 * 512
#define PLANE_F4  1024      // 64*64 / 4 (64 rows x 16 float4)
#define PLANE_BYTES 16384
#define THREADS   256

__device__ __forceinline__ uint32_t smem_u32(const void* p) {
    return (uint32_t)__cvta_generic_to_shared(p);
}

__device__ __forceinline__ uint64_t policy_evict_first() {
    uint64_t pol;
    asm volatile("createpolicy.fractional.L2::evict_first.b64 %0, 1.0;" : "=l"(pol));
    return pol;
}

__device__ __forceinline__ uint64_t policy_evict_last() {
    uint64_t pol;
    asm volatile("createpolicy.fractional.L2::evict_last.b64 %0, 1.0;" : "=l"(pol));
    return pol;
}

__device__ __forceinline__ void bulk_store_ef(void* gdst, uint32_t ssrc, uint64_t pol) {
    asm volatile(
        "cp.async.bulk.global.shared::cta.bulk_group.L2::cache_hint [%0], [%1], %2, %3;"
        :: "l"(gdst), "r"(ssrc), "n"(PLANE_BYTES), "l"(pol) : "memory");
    asm volatile("cp.async.bulk.commit_group;" ::: "memory");
}

__device__ __forceinline__ void fence_async() {
    asm volatile("fence.proxy.async.shared::cta;" ::: "memory");
}

template <int N>
__device__ __forceinline__ void bulk_wait() {
    asm volatile("cp.async.bulk.wait_group %0;" :: "n"(N) : "memory");
}

__device__ __forceinline__ float4 ldg_evict_last(const float4* p, uint64_t pol) {
    float4 v;
    asm volatile("ld.global.L2::cache_hint.v4.f32 {%0,%1,%2,%3}, [%4], %5;"
                 : "=f"(v.x), "=f"(v.y), "=f"(v.z), "=f"(v.w)
                 : "l"(p), "l"(pol));
    return v;
}

__device__ __forceinline__ float4 v4max(float4 a, float4 b) {
    return make_float4(fmaxf(a.x, b.x), fmaxf(a.y, b.y),
                       fmaxf(a.z, b.z), fmaxf(a.w, b.w));
}

// 5-wide horizontal max over [p.z p.w | c.x c.y c.z c.w | n.x n.y]
__device__ __forceinline__ float4 hmax5(float4 p, float4 c, float4 n) {
    float m01 = fmaxf(c.x, c.y);
    float m23 = fmaxf(c.z, c.w);
    float m0123 = fmaxf(m01, m23);
    float4 o;
    o.x = fmaxf(fmaxf(p.z, p.w), fmaxf(m01, c.z));
    o.y = fmaxf(p.w, m0123);
    o.z = fmaxf(m0123, n.x);
    o.w = fmaxf(fmaxf(c.y, m23), fmaxf(n.x, n.y));
    return o;
}

__global__ __launch_bounds__(THREADS, 5)
void spp_kernel(const float4* __restrict__ in, float4* __restrict__ out) {
    __shared__ float4 S0[PLANE_F4];
    __shared__ float4 S1[PLANE_F4];

    const float NEG = __int_as_float(0xff800000);  // -inf
    const float4 NEG4 = make_float4(NEG, NEG, NEG, NEG);

    const int plane = blockIdx.x;           // n*512 + c
    const int n = plane >> 9;
    const int c = plane & 511;
    const int tid = threadIdx.x;
    const int xg = tid & 15;                // float4 column 0..15
    const int yg = tid >> 4;                // row-strip 0..15 (rows 4*yg..4*yg+3)
    const int base = ((yg << 2) << 4) + xg; // index of row 4*yg, column xg

    const float4* src = in + (size_t)plane * PLANE_F4;
    float4* out0 = out + ((size_t)n * 2048 + c) * PLANE_F4;

    const uint64_t pol_ef = policy_evict_first();
    const uint64_t pol_el = policy_evict_last();

    // ---- load strip into S0 (evict_last); copy section via bulk store ----
    float4 v[4];
    #pragma unroll
    for (int r = 0; r < 4; r++) {
        int t = base + (r << 4);
        v[r] = ldg_evict_last(&src[t], pol_el);
        S0[t] = v[r];
    }
    __syncthreads();
    if (tid == 0) {
        fence_async();
        bulk_store_ef(out0, smem_u32(S0), pol_ef);   // W_copy (reads S0)
    }

    float4* cur = S0;                       // holds current v-plane
    float4* nxt = S1;

    // ---- three cascaded pool5 stages ----
    #pragma unroll
    for (int pool = 0; pool < 3; pool++) {
        // horizontal pass: center from regs, neighbor columns from cur
        float4 h[4];
        #pragma unroll
        for (int r = 0; r < 4; r++) {
            int t = base + (r << 4);
            float4 p  = (xg > 0)  ? cur[t - 1] : NEG4;
            float4 nx = (xg < 15) ? cur[t + 1] : NEG4;
            h[r] = hmax5(p, v[r], nx);
        }
        // before overwriting nxt: its previous bulk store (2 groups back) must be done
        if (tid == 0) bulk_wait<1>();
        __syncthreads();
        #pragma unroll
        for (int r = 0; r < 4; r++) nxt[base + (r << 4)] = h[r];
        __syncthreads();

        // vertical pass: my 4 h-rows in regs + 2 above + 2 below from nxt
        float4 u0 = (yg > 0)  ? nxt[base - 32] : NEG4;  // row 4yg-2
        float4 u1 = (yg > 0)  ? nxt[base - 16] : NEG4;  // row 4yg-1
        float4 d0 = (yg < 15) ? nxt[base + 64] : NEG4;  // row 4yg+4
        float4 d1 = (yg < 15) ? nxt[base + 80] : NEG4;  // row 4yg+5

        float4 m12 = v4max(h[1], h[2]);                 // shared subexpression
        v[0] = v4max(v4max(u0, u1), v4max(h[0], m12));
        v[1] = v4max(v4max(u1, h[0]), v4max(m12, h[3]));
        v[2] = v4max(v4max(h[0], m12), v4max(h[3], d0));
        v[3] = v4max(v4max(m12, h[3]), v4max(d0, d1));

        __syncthreads();                    // all v-pass reads of nxt done
        #pragma unroll
        for (int r = 0; r < 4; r++) nxt[base + (r << 4)] = v[r];
        __syncthreads();                    // v-plane complete in nxt
        if (tid == 0) {
            fence_async();
            bulk_store_ef(out0 + (size_t)(pool + 1) * 512 * PLANE_F4,
                          smem_u32(nxt), pol_ef);
        }
        // swap roles: nxt (now v-plane) becomes cur
        float4* tmp = cur; cur = nxt; nxt = tmp;
    }

    // drain remaining bulk stores before CTA exit
    if (tid == 0) bulk_wait<0>();
}

extern "C" void kernel_launch(void* const* d_in, const int* in_sizes, int n_in,
                              void* d_out, int out_size) {
    const float4* x = (const float4*)d_in[0];
    float4* out = (float4*)d_out;
    spp_kernel<<<NPLANES, THREADS>>>(x, out);
}

// round 9
// speedup vs baseline: 1.0306x; 1.0003x over previous
#include <cuda_runtime.h>
#include <cstdint>

// SPP: out = concat(x, pool5(x), pool9(x), pool13(x)) along channels.
// pool9 = pool5(pool5(x)), pool13 = pool5(pool9); separable 1-D passes.
// R9 = R8 + horizontal pass via warp shuffles (xg adjacency is intra-warp):
//     removes all h-pass LDS; smem ops per pool 20 -> 12 per thread.

#define NPLANES   8192      // 16 * 512
#define PLANE_F4  1024      // 64*64 / 4 (64 rows x 16 float4)
#define PLANE_BYTES 16384
#define THREADS   256
#define FULL      0xffffffffu

__device__ __forceinline__ uint32_t smem_u32(const void* p) {
    return (uint32_t)__cvta_generic_to_shared(p);
}
__device__ __forceinline__ uint64_t policy_evict_first() {
    uint64_t pol;
    asm volatile("createpolicy.fractional.L2::evict_first.b64 %0, 1.0;" : "=l"(pol));
    return pol;
}
__device__ __forceinline__ uint64_t policy_evict_last() {
    uint64_t pol;
    asm volatile("createpolicy.fractional.L2::evict_last.b64 %0, 1.0;" : "=l"(pol));
    return pol;
}
__device__ __forceinline__ void bulk_store_ef(void* gdst, uint32_t ssrc, uint64_t pol) {
    asm volatile(
        "cp.async.bulk.global.shared::cta.bulk_group.L2::cache_hint [%0], [%1], %2, %3;"
        :: "l"(gdst), "r"(ssrc), "n"(PLANE_BYTES), "l"(pol) : "memory");
    asm volatile("cp.async.bulk.commit_group;" ::: "memory");
}
__device__ __forceinline__ void fence_async() {
    asm volatile("fence.proxy.async.shared::cta;" ::: "memory");
}
template <int N>
__device__ __forceinline__ void bulk_wait() {
    asm volatile("cp.async.bulk.wait_group %0;" :: "n"(N) : "memory");
}
__device__ __forceinline__ float4 ldg_evict_last(const float4* p, uint64_t pol) {
    float4 v;
    asm volatile("ld.global.L2::cache_hint.v4.f32 {%0,%1,%2,%3}, [%4], %5;"
                 : "=f"(v.x), "=f"(v.y), "=f"(v.z), "=f"(v.w)
                 : "l"(p), "l"(pol));
    return v;
}

__device__ __forceinline__ float4 v4max(float4 a, float4 b) {
    return make_float4(fmaxf(a.x, b.x), fmaxf(a.y, b.y),
                       fmaxf(a.z, b.z), fmaxf(a.w, b.w));
}

// 5-wide horizontal max using shuffles: window [pz pw | c.x..c.w | nx ny]
__device__ __forceinline__ float4 hmax5_shfl(float4 cu, int xg) {
    const float NEG = __int_as_float(0xff800000);
    float pz = __shfl_up_sync(FULL, cu.z, 1);
    float pw = __shfl_up_sync(FULL, cu.w, 1);
    float nx = __shfl_down_sync(FULL, cu.x, 1);
    float ny = __shfl_down_sync(FULL, cu.y, 1);
    if (xg == 0)  { pz = NEG; pw = NEG; }
    if (xg == 15) { nx = NEG; ny = NEG; }
    float m01 = fmaxf(cu.x, cu.y);
    float m23 = fmaxf(cu.z, cu.w);
    float m0123 = fmaxf(m01, m23);
    float4 o;
    o.x = fmaxf(fmaxf(pz, pw), fmaxf(m01, cu.z));
    o.y = fmaxf(pw, m0123);
    o.z = fmaxf(m0123, nx);
    o.w = fmaxf(fmaxf(cu.y, m23), fmaxf(nx, ny));
    return o;
}

__global__ __launch_bounds__(THREADS, 5)
void spp_kernel(const float4* __restrict__ in, float4* __restrict__ out) {
    __shared__ float4 S0[PLANE_F4];
    __shared__ float4 S1[PLANE_F4];

    const float NEG = __int_as_float(0xff800000);  // -inf
    const float4 NEG4 = make_float4(NEG, NEG, NEG, NEG);

    const int plane = blockIdx.x;           // n*512 + c
    const int n = plane >> 9;
    const int c = plane & 511;
    const int tid = threadIdx.x;
    const int xg = tid & 15;                // float4 column 0..15 (intra-warp!)
    const int yg = tid >> 4;                // row-strip 0..15 (rows 4*yg..4*yg+3)
    const int base = ((yg << 2) << 4) + xg; // index of row 4*yg, column xg

    const float4* src = in + (size_t)plane * PLANE_F4;
    float4* out0 = out + ((size_t)n * 2048 + c) * PLANE_F4;

    const uint64_t pol_ef = policy_evict_first();
    const uint64_t pol_el = policy_evict_last();

    // ---- load strip into regs + S0; copy section via bulk store from S0 ----
    float4 v[4];
    #pragma unroll
    for (int r = 0; r < 4; r++) {
        int t = base + (r << 4);
        v[r] = ldg_evict_last(&src[t], pol_el);
        S0[t] = v[r];
    }
    __syncthreads();
    if (tid == 0) {
        fence_async();
        bulk_store_ef(out0, smem_u32(S0), pol_ef);   // W_copy (reads S0)
    }

    float4* cur = S0;   // source of most recent pending bulk store
    float4* nxt = S1;   // scratch for this pool (h-exchange, then v / bulk src)

    // ---- three cascaded pool5 stages ----
    #pragma unroll
    for (int pool = 0; pool < 3; pool++) {
        // horizontal pass: pure register/shuffle, no smem
        float4 h[4];
        #pragma unroll
        for (int r = 0; r < 4; r++) h[r] = hmax5_shfl(v[r], xg);

        // before overwriting nxt: its previous bulk store (2 groups back) done
        if (tid == 0) bulk_wait<1>();
        __syncthreads();
        #pragma unroll
        for (int r = 0; r < 4; r++) nxt[base + (r << 4)] = h[r];
        __syncthreads();

        // vertical pass: my 4 h-rows in regs + 2 above + 2 below from nxt
        float4 u0 = (yg > 0)  ? nxt[base - 32] : NEG4;  // row 4yg-2
        float4 u1 = (yg > 0)  ? nxt[base - 16] : NEG4;  // row 4yg-1
        float4 d0 = (yg < 15) ? nxt[base + 64] : NEG4;  // row 4yg+4
        float4 d1 = (yg < 15) ? nxt[base + 80] : NEG4;  // row 4yg+5

        float4 m12 = v4max(h[1], h[2]);                 // shared subexpression
        v[0] = v4max(v4max(u0, u1), v4max(h[0], m12));
        v[1] = v4max(v4max(u1, h[0]), v4max(m12, h[3]));
        v[2] = v4max(v4max(h[0], m12), v4max(h[3], d0));
        v[3] = v4max(v4max(m12, h[3]), v4max(d0, d1));

        __syncthreads();                    // all v-pass reads of nxt done
        #pragma unroll
        for (int r = 0; r < 4; r++) nxt[base + (r << 4)] = v[r];
        __syncthreads();                    // v-plane complete in nxt
        if (tid == 0) {
            fence_async();
            bulk_store_ef(out0 + (size_t)(pool + 1) * 512 * PLANE_F4,
                          smem_u32(nxt), pol_ef);
        }
        // swap: nxt becomes the pending-store buffer; old cur is reusable
        float4* tmp = cur; cur = nxt; nxt = tmp;
    }

    // drain remaining bulk stores before CTA exit
    if (tid == 0) bulk_wait<0>();
}

extern "C" void kernel_launch(void* const* d_in, const int* in_sizes, int n_in,
                              void* d_out, int out_size) {
    const float4* x = (const float4*)d_in[0];
    float4* out = (float4*)d_out;
    spp_kernel<<<NPLANES, THREADS>>>(x, out);
}

// round 10
// speedup vs baseline: 1.0329x; 1.0022x over previous
#include <cuda_runtime.h>
#include <cstdint>

// SPP: out = concat(x, pool5(x), pool9(x), pool13(x)) along channels.
// pool9 = pool5(pool5(x)), pool13 = pool5(pool9); separable 1-D passes.
// R10 = R9 (shuffle h-pass, bulk-group stores, L2 policy split) with
//       __launch_bounds__(256, 6): 6 blocks/SM (203KB smem, 61.4K regs)
//       to cover sync/memory latency and keep the DRAM write stream fed.

#define NPLANES   8192      // 16 * 512
#define PLANE_F4  1024      // 64*64 / 4 (64 rows x 16 float4)
#define PLANE_BYTES 16384
#define THREADS   256
#define FULL      0xffffffffu

__device__ __forceinline__ uint32_t smem_u32(const void* p) {
    return (uint32_t)__cvta_generic_to_shared(p);
}
__device__ __forceinline__ uint64_t policy_evict_first() {
    uint64_t pol;
    asm volatile("createpolicy.fractional.L2::evict_first.b64 %0, 1.0;" : "=l"(pol));
    return pol;
}
__device__ __forceinline__ uint64_t policy_evict_last() {
    uint64_t pol;
    asm volatile("createpolicy.fractional.L2::evict_last.b64 %0, 1.0;" : "=l"(pol));
    return pol;
}
__device__ __forceinline__ void bulk_store_ef(void* gdst, uint32_t ssrc, uint64_t pol) {
    asm volatile(
        "cp.async.bulk.global.shared::cta.bulk_group.L2::cache_hint [%0], [%1], %2, %3;"
        :: "l"(gdst), "r"(ssrc), "n"(PLANE_BYTES), "l"(pol) : "memory");
    asm volatile("cp.async.bulk.commit_group;" ::: "memory");
}
__device__ __forceinline__ void fence_async() {
    asm volatile("fence.proxy.async.shared::cta;" ::: "memory");
}
template <int N>
__device__ __forceinline__ void bulk_wait() {
    asm volatile("cp.async.bulk.wait_group %0;" :: "n"(N) : "memory");
}
__device__ __forceinline__ float4 ldg_evict_last(const float4* p, uint64_t pol) {
    float4 v;
    asm volatile("ld.global.L2::cache_hint.v4.f32 {%0,%1,%2,%3}, [%4], %5;"
                 : "=f"(v.x), "=f"(v.y), "=f"(v.z), "=f"(v.w)
                 : "l"(p), "l"(pol));
    return v;
}

__device__ __forceinline__ float4 v4max(float4 a, float4 b) {
    return make_float4(fmaxf(a.x, b.x), fmaxf(a.y, b.y),
                       fmaxf(a.z, b.z), fmaxf(a.w, b.w));
}

// 5-wide horizontal max using shuffles: window [pz pw | c.x..c.w | nx ny]
__device__ __forceinline__ float4 hmax5_shfl(float4 cu, int xg) {
    const float NEG = __int_as_float(0xff800000);
    float pz = __shfl_up_sync(FULL, cu.z, 1);
    float pw = __shfl_up_sync(FULL, cu.w, 1);
    float nx = __shfl_down_sync(FULL, cu.x, 1);
    float ny = __shfl_down_sync(FULL, cu.y, 1);
    if (xg == 0)  { pz = NEG; pw = NEG; }
    if (xg == 15) { nx = NEG; ny = NEG; }
    float m01 = fmaxf(cu.x, cu.y);
    float m23 = fmaxf(cu.z, cu.w);
    float m0123 = fmaxf(m01, m23);
    float4 o;
    o.x = fmaxf(fmaxf(pz, pw), fmaxf(m01, cu.z));
    o.y = fmaxf(pw, m0123);
    o.z = fmaxf(m0123, nx);
    o.w = fmaxf(fmaxf(cu.y, m23), fmaxf(nx, ny));
    return o;
}

__global__ __launch_bounds__(THREADS, 6)
void spp_kernel(const float4* __restrict__ in, float4* __restrict__ out) {
    __shared__ float4 S0[PLANE_F4];
    __shared__ float4 S1[PLANE_F4];

    const float NEG = __int_as_float(0xff800000);  // -inf
    const float4 NEG4 = make_float4(NEG, NEG, NEG, NEG);

    const int plane = blockIdx.x;           // n*512 + c
    const int n = plane >> 9;
    const int c = plane & 511;
    const int tid = threadIdx.x;
    const int xg = tid & 15;                // float4 column 0..15 (intra-warp)
    const int yg = tid >> 4;                // row-strip 0..15 (rows 4*yg..4*yg+3)
    const int base = ((yg << 2) << 4) + xg; // index of row 4*yg, column xg

    const float4* src = in + (size_t)plane * PLANE_F4;
    float4* out0 = out + ((size_t)n * 2048 + c) * PLANE_F4;

    const uint64_t pol_ef = policy_evict_first();
    const uint64_t pol_el = policy_evict_last();

    // ---- load strip into regs + S0; copy section via bulk store from S0 ----
    float4 v[4];
    #pragma unroll
    for (int r = 0; r < 4; r++) {
        int t = base + (r << 4);
        v[r] = ldg_evict_last(&src[t], pol_el);
        S0[t] = v[r];
    }
    __syncthreads();
    if (tid == 0) {
        fence_async();
        bulk_store_ef(out0, smem_u32(S0), pol_ef);   // W_copy (reads S0)
    }

    float4* cur = S0;   // source of most recent pending bulk store
    float4* nxt = S1;   // scratch for this pool (h-exchange, then v / bulk src)

    // ---- three cascaded pool5 stages ----
    #pragma unroll
    for (int pool = 0; pool < 3; pool++) {
        // horizontal pass: pure register/shuffle, no smem
        float4 h[4];
        #pragma unroll
        for (int r = 0; r < 4; r++) h[r] = hmax5_shfl(v[r], xg);

        // before overwriting nxt: its previous bulk store (2 groups back) done
        if (tid == 0) bulk_wait<1>();
        __syncthreads();
        #pragma unroll
        for (int r = 0; r < 4; r++) nxt[base + (r << 4)] = h[r];
        __syncthreads();

        // vertical pass: my 4 h-rows in regs + 2 above + 2 below from nxt
        float4 u0 = (yg > 0)  ? nxt[base - 32] : NEG4;  // row 4yg-2
        float4 u1 = (yg > 0)  ? nxt[base - 16] : NEG4;  // row 4yg-1
        float4 d0 = (yg < 15) ? nxt[base + 64] : NEG4;  // row 4yg+4
        float4 d1 = (yg < 15) ? nxt[base + 80] : NEG4;  // row 4yg+5

        float4 m12 = v4max(h[1], h[2]);                 // shared subexpression
        v[0] = v4max(v4max(u0, u1), v4max(h[0], m12));
        v[1] = v4max(v4max(u1, h[0]), v4max(m12, h[3]));
        v[2] = v4max(v4max(h[0], m12), v4max(h[3], d0));
        v[3] = v4max(v4max(m12, h[3]), v4max(d0, d1));

        __syncthreads();                    // all v-pass reads of nxt done
        #pragma unroll
        for (int r = 0; r < 4; r++) nxt[base + (r << 4)] = v[r];
        __syncthreads();                    // v-plane complete in nxt
        if (tid == 0) {
            fence_async();
            bulk_store_ef(out0 + (size_t)(pool + 1) * 512 * PLANE_F4,
                          smem_u32(nxt), pol_ef);
        }
        // swap: nxt becomes the pending-store buffer; old cur is reusable
        float4* tmp = cur; cur = nxt; nxt = tmp;
    }

    // drain remaining bulk stores before CTA exit
    if (tid == 0) bulk_wait<0>();
}

extern "C" void kernel_launch(void* const* d_in, const int* in_sizes, int n_in,
                              void* d_out, int out_size) {
    const float4* x = (const float4*)d_in[0];
    float4* out = (float4*)d_out;
    spp_kernel<<<NPLANES, THREADS>>>(x, out);
}